// round 2
// baseline (speedup 1.0000x reference)
#include <cuda_runtime.h>
#include <cuda_bf16.h>

#define NE 20000
#define NN 1000

// permuted row order: m=0 rows(5), +1(4), -1(4), +2(3), -2(3)
__constant__ int c_PERM[19]   = {0,2,6,11,16, 3,7,12,17, 1,5,10,15, 8,13,18, 4,9,14};
__constant__ int c_RADOFF[19] = {0,128,256,384,512, 640,768,896,1024, 640,768,896,1024,
                                 1152,1280,1408, 1152,1280,1408};

// ----------------- scratch (__device__ globals; no runtime alloc) -----------
__device__ __align__(16) float g_hid [(size_t)NE*64];
__device__ __align__(16) float g_rad [(size_t)NE*1536];
__device__ __align__(16) float g_sm  [(size_t)NE*2432];   // wigner out, permuted, rad-scaled
__device__ __align__(16) float g_tmp0[(size_t)NE*896];    // conv1 gemm0 out (alpha|gate|m0)
__device__ __align__(16) float g_h1  [(size_t)NE*1216];   // conv1 out rows 5..18 (64/row)
__device__ __align__(16) float g_h2  [(size_t)NE*1216];   // grid-stage out (19x64 permuted)
__device__ __align__(16) float g_h3  [(size_t)NE*2432];   // conv2 out (19x128 permuted)
__device__ __align__(16) float g_alf [(size_t)NE*8];
__device__ unsigned int        g_amax[NN*8];
__device__ float               g_den [NN*8];
__device__ __align__(16) float g_node[(size_t)NN*3200];

// ----------------- helpers --------------------------------------------------
__device__ __forceinline__ float sigmoidf_(float x){ return 1.f/(1.f+__expf(-x)); }
__device__ __forceinline__ float siluf_(float x){ return x*sigmoidf_(x); }
__device__ __forceinline__ float slrelu_(float x){ return 0.6f*x + 0.4f*x*(2.f*sigmoidf_(x)-1.f); }

// reduce over 64 threads (2 warps), blockDim==64
__device__ __forceinline__ float red64(float v, float* sbuf, int t){
    #pragma unroll
    for (int o=16;o;o>>=1) v += __shfl_xor_sync(0xffffffffu, v, o);
    if ((t&31)==0) sbuf[t>>5] = v;
    __syncthreads();
    float r = sbuf[0]+sbuf[1];
    __syncthreads();
    return r;
}

// ----------------- init -----------------------------------------------------
__global__ void k_init(float* node, unsigned int* amax, float* den){
    int i = blockIdx.x*256 + threadIdx.x;
    if (i < NN*3200) node[i] = 0.f;
    if (i < NN*8) { amax[i] = 0u; den[i] = 0.f; }
}

// ----------------- radial layers 1+2 (LN + silu) ----------------------------
__global__ void k_radial(const float* __restrict__ ed,
                         const float* __restrict__ w1, const float* __restrict__ b1,
                         const float* __restrict__ g1, const float* __restrict__ be1,
                         const float* __restrict__ w2, const float* __restrict__ b2,
                         const float* __restrict__ g2, const float* __restrict__ be2,
                         float* __restrict__ outp)
{
    __shared__ float w1t[64*64], w2t[64*64];
    __shared__ float xin[64], hmid[64];
    __shared__ float sbuf[2];
    int t = threadIdx.x; // 64
    for (int i = t; i < 4096; i += 64) {
        int r = i >> 6, c = i & 63;
        w1t[c*64 + r] = w1[i];
        w2t[c*64 + r] = w2[i];
    }
    __syncthreads();
    for (int e = blockIdx.x; e < NE; e += gridDim.x) {
        xin[t] = ed[(size_t)e*64 + t];
        __syncthreads();
        // layer 1
        float acc = b1[t];
        #pragma unroll 8
        for (int k = 0; k < 64; k++) acc += xin[k]*w1t[k*64+t];
        float mu = red64(acc, sbuf, t) * (1.f/64.f);
        float d = acc - mu;
        float var = red64(d*d, sbuf, t) * (1.f/64.f);
        float v = d*rsqrtf(var+1e-5f)*g1[t] + be1[t];
        hmid[t] = siluf_(v);
        __syncthreads();
        // layer 2
        acc = b2[t];
        #pragma unroll 8
        for (int k = 0; k < 64; k++) acc += hmid[k]*w2t[k*64+t];
        mu = red64(acc, sbuf, t) * (1.f/64.f);
        d = acc - mu;
        var = red64(d*d, sbuf, t) * (1.f/64.f);
        v = d*rsqrtf(var+1e-5f)*g2[t] + be2[t];
        outp[(size_t)e*64 + t] = siluf_(v);
        __syncthreads();
    }
}

// ----------------- real GEMM: C[M,N] = A[M,K] @ W[N,K]^T + bias -------------
__global__ void k_gemm(const float* __restrict__ A, int lda,
                       const float* __restrict__ W, const float* __restrict__ bias,
                       float* __restrict__ C, int ldc,
                       int M, int N, int K)
{
    __shared__ float As[16][68];
    __shared__ float Ws[16][68];
    int bm = blockIdx.x * 64, bn = blockIdx.y * 64;
    int tid = threadIdx.x;
    int tx = tid & 15, ty = tid >> 4;
    int lrow = tid >> 2, lq = tid & 3;
    float acc[4][4] = {};
    int arow = bm + lrow;
    const float* Ap = A + (size_t)arow * lda + lq*4;
    const float* Wp = W + (size_t)(bn + lrow) * K + lq*4;
    for (int k0 = 0; k0 < K; k0 += 16) {
        float4 av = make_float4(0.f,0.f,0.f,0.f);
        if (arow < M) av = *(const float4*)(Ap + k0);
        float4 wv = *(const float4*)(Wp + k0);
        __syncthreads();
        As[lq*4+0][lrow]=av.x; As[lq*4+1][lrow]=av.y; As[lq*4+2][lrow]=av.z; As[lq*4+3][lrow]=av.w;
        Ws[lq*4+0][lrow]=wv.x; Ws[lq*4+1][lrow]=wv.y; Ws[lq*4+2][lrow]=wv.z; Ws[lq*4+3][lrow]=wv.w;
        __syncthreads();
        #pragma unroll
        for (int k = 0; k < 16; k++) {
            float4 a = *(const float4*)&As[k][ty*4];
            float4 b = *(const float4*)&Ws[k][tx*4];
            acc[0][0]+=a.x*b.x; acc[0][1]+=a.x*b.y; acc[0][2]+=a.x*b.z; acc[0][3]+=a.x*b.w;
            acc[1][0]+=a.y*b.x; acc[1][1]+=a.y*b.y; acc[1][2]+=a.y*b.z; acc[1][3]+=a.y*b.w;
            acc[2][0]+=a.z*b.x; acc[2][1]+=a.z*b.y; acc[2][2]+=a.z*b.z; acc[2][3]+=a.z*b.w;
            acc[3][0]+=a.w*b.x; acc[3][1]+=a.w*b.y; acc[3][2]+=a.w*b.z; acc[3][3]+=a.w*b.w;
        }
    }
    #pragma unroll
    for (int i=0;i<4;i++) {
        int m = bm + ty*4 + i;
        if (m < M) {
            float* cr = C + (size_t)m*ldc + bn + tx*4;
            #pragma unroll
            for (int j=0;j<4;j++) cr[j] = acc[i][j] + bias[bn + tx*4 + j];
        }
    }
}

// --------- complex GEMM: (Cp + i Cm) = (Are + i Aim) @ (Wr + i Wi)^T --------
__global__ void k_cgemm(const float* __restrict__ Are, const float* __restrict__ Aim, int lda,
                        const float* __restrict__ W, int wioff,
                        float* __restrict__ Cp, float* __restrict__ Cm, int ldc,
                        int M, int N, int K)
{
    __shared__ float Ars[16][68], Ais[16][68], Wrs[16][68], Wis[16][68];
    int bm = blockIdx.x * 64, bn = blockIdx.y * 64;
    int tid = threadIdx.x;
    int tx = tid & 15, ty = tid >> 4;
    int lrow = tid >> 2, lq = tid & 3;
    float accr[4][4] = {}, acci[4][4] = {};
    int arow = bm + lrow;
    const float* Arp = Are + (size_t)arow * lda + lq*4;
    const float* Aip = Aim + (size_t)arow * lda + lq*4;
    const float* Wrp = W + (size_t)(bn + lrow) * K + lq*4;
    const float* Wip = W + (size_t)wioff + (size_t)(bn + lrow) * K + lq*4;
    for (int k0 = 0; k0 < K; k0 += 16) {
        float4 arv = make_float4(0.f,0.f,0.f,0.f), aiv = arv;
        if (arow < M) { arv = *(const float4*)(Arp + k0); aiv = *(const float4*)(Aip + k0); }
        float4 wrv = *(const float4*)(Wrp + k0);
        float4 wiv = *(const float4*)(Wip + k0);
        __syncthreads();
        Ars[lq*4+0][lrow]=arv.x; Ars[lq*4+1][lrow]=arv.y; Ars[lq*4+2][lrow]=arv.z; Ars[lq*4+3][lrow]=arv.w;
        Ais[lq*4+0][lrow]=aiv.x; Ais[lq*4+1][lrow]=aiv.y; Ais[lq*4+2][lrow]=aiv.z; Ais[lq*4+3][lrow]=aiv.w;
        Wrs[lq*4+0][lrow]=wrv.x; Wrs[lq*4+1][lrow]=wrv.y; Wrs[lq*4+2][lrow]=wrv.z; Wrs[lq*4+3][lrow]=wrv.w;
        Wis[lq*4+0][lrow]=wiv.x; Wis[lq*4+1][lrow]=wiv.y; Wis[lq*4+2][lrow]=wiv.z; Wis[lq*4+3][lrow]=wiv.w;
        __syncthreads();
        #pragma unroll
        for (int k = 0; k < 16; k++) {
            float4 a4 = *(const float4*)&Ars[k][ty*4];
            float4 i4 = *(const float4*)&Ais[k][ty*4];
            float4 r4 = *(const float4*)&Wrs[k][tx*4];
            float4 w4 = *(const float4*)&Wis[k][tx*4];
            float ar[4] = {a4.x,a4.y,a4.z,a4.w};
            float ai[4] = {i4.x,i4.y,i4.z,i4.w};
            float wr[4] = {r4.x,r4.y,r4.z,r4.w};
            float wi[4] = {w4.x,w4.y,w4.z,w4.w};
            #pragma unroll
            for (int i=0;i<4;i++)
                #pragma unroll
                for (int j=0;j<4;j++) {
                    accr[i][j] += ar[i]*wr[j] - ai[i]*wi[j];
                    acci[i][j] += ai[i]*wr[j] + ar[i]*wi[j];
                }
        }
    }
    #pragma unroll
    for (int i=0;i<4;i++) {
        int m = bm + ty*4 + i;
        if (m < M) {
            float* cp = Cp + (size_t)m*ldc + bn + tx*4;
            float* cm = Cm + (size_t)m*ldc + bn + tx*4;
            #pragma unroll
            for (int j=0;j<4;j++) { cp[j] = accr[i][j]; cm[j] = acci[i][j]; }
        }
    }
}

// ---------- wigner: msg = perm(wigner @ [x_src|x_dst]) * rad ----------------
__global__ void k_wigner(const float* __restrict__ x, const int* __restrict__ ei,
                         const float* __restrict__ wig, const float* __restrict__ rad,
                         float* __restrict__ sm)
{
    __shared__ float msg[25][128];
    __shared__ float wg[19][25];
    int e = blockIdx.x;
    int t = threadIdx.x; // 128
    int src = ei[e], dst = ei[NE + e];
    const float* xs = x + (size_t)src*1600;
    const float* xd = x + (size_t)dst*1600;
    int c = t & 63;
    if (t < 64) { for (int j=0;j<25;j++) msg[j][t] = xs[j*64+c]; }
    else        { for (int j=0;j<25;j++) msg[j][t] = xd[j*64+c]; }
    for (int i = t; i < 475; i += 128) {
        int p = i/25, j = i%25;
        wg[p][j] = wig[(size_t)e*475 + (size_t)c_PERM[p]*25 + j];
    }
    __syncthreads();
    const float* re = rad + (size_t)e*1536;
    float* so = sm + (size_t)e*2432;
    #pragma unroll
    for (int p = 0; p < 19; p++) {
        float acc = 0.f;
        #pragma unroll
        for (int j = 0; j < 25; j++) acc += wg[p][j]*msg[j][t];
        so[p*128 + t] = acc * re[c_RADOFF[p] + t];
    }
}

// ---------- grid stage: silu-gated S2 pointwise -----------------------------
__global__ void k_grid(const float* __restrict__ tmp0, const float* __restrict__ h1,
                       const float* __restrict__ tgrid, const float* __restrict__ fgrid,
                       float* __restrict__ h2)
{
    __shared__ float tg[100][20];
    __shared__ float fg[100][20];
    __shared__ float h[2][19][64];
    int t = threadIdx.x; // 128
    for (int i = t; i < 1900; i += 128) {
        int ba = i / 19, p = i % 19;
        tg[ba][p] = tgrid[ba*19 + c_PERM[p]];
        fg[ba][p] = fgrid[ba*19 + c_PERM[p]];
    }
    int el = t >> 6, c = t & 63;
    int e = blockIdx.x*2 + el;
    const float* t0 = tmp0 + (size_t)e*896;
    #pragma unroll
    for (int p = 0; p < 5; p++) h[el][p][c] = t0[576 + p*64 + c];
    const float* hh = h1 + (size_t)e*1216;
    #pragma unroll
    for (int p = 5; p < 19; p++) h[el][p][c] = hh[p*64 + c];
    __syncthreads();
    float s2[19];
    #pragma unroll
    for (int p=0;p<19;p++) s2[p]=0.f;
    for (int ba = 0; ba < 100; ba++) {
        float g = 0.f;
        #pragma unroll
        for (int p = 0; p < 19; p++) g += tg[ba][p]*h[el][p][c];
        g = siluf_(g);
        #pragma unroll
        for (int p = 0; p < 19; p++) s2[p] += fg[ba][p]*g;
    }
    float* o = h2 + (size_t)e*1216;
    o[c] = siluf_(t0[512 + c]);          // row 0 := silu(gate)
    #pragma unroll
    for (int p = 1; p < 19; p++) o[p*64 + c] = s2[p];
}

// ---------- alpha: LN + smooth-leaky-relu + dot, atomicMax ------------------
__global__ void k_alpha1(const float* __restrict__ tmp0, const int* __restrict__ ei,
                         const float* __restrict__ lng, const float* __restrict__ lnb,
                         const float* __restrict__ adot,
                         float* __restrict__ alpha, unsigned int* __restrict__ amax)
{
    int e = blockIdx.x;
    int w = threadIdx.x >> 5, lane = threadIdx.x & 31; // 8 warps = 8 heads
    const float* a = tmp0 + (size_t)e*896 + w*64;
    float v0 = a[lane], v1 = a[lane+32];
    float s = v0+v1;
    #pragma unroll
    for (int o=16;o;o>>=1) s += __shfl_xor_sync(0xffffffffu, s, o);
    float mu = s * (1.f/64.f);
    float d0=v0-mu, d1=v1-mu;
    float q = d0*d0+d1*d1;
    #pragma unroll
    for (int o=16;o;o>>=1) q += __shfl_xor_sync(0xffffffffu, q, o);
    float rstd = rsqrtf(q*(1.f/64.f) + 1e-5f);
    float x0 = slrelu_(d0*rstd*lng[lane]+lnb[lane]);
    float x1 = slrelu_(d1*rstd*lng[lane+32]+lnb[lane+32]);
    float p = x0*adot[w*64+lane] + x1*adot[w*64+lane+32];
    #pragma unroll
    for (int o=16;o;o>>=1) p += __shfl_xor_sync(0xffffffffu, p, o);
    if (lane == 0) {
        alpha[e*8+w] = p;
        int dst = ei[NE + e];
        unsigned int enc = __float_as_uint(p);
        enc = (enc & 0x80000000u) ? ~enc : (enc | 0x80000000u);
        atomicMax(&amax[dst*8+w], enc);
    }
}

__global__ void k_alpha2(float* __restrict__ alpha, const int* __restrict__ ei,
                         const unsigned int* __restrict__ amax, float* __restrict__ den)
{
    int i = blockIdx.x*256 + threadIdx.x;
    if (i >= NE*8) return;
    int e = i >> 3, h = i & 7;
    int dst = ei[NE + e];
    unsigned int u = amax[dst*8+h];
    float m = (u & 0x80000000u) ? __uint_as_float(u & 0x7FFFFFFFu) : __uint_as_float(~u);
    float ex = __expf(alpha[i] - m);
    alpha[i] = ex;
    atomicAdd(&den[dst*8+h], ex);
}

// ---------- attention weight + wigner_inv + segment-sum ---------------------
__global__ void k_attn(const float* __restrict__ h3, const float* __restrict__ winv,
                       const float* __restrict__ alpha, const float* __restrict__ den,
                       const int* __restrict__ ei, float* __restrict__ node)
{
    __shared__ float m[19][128];
    __shared__ float wi[25][20];
    __shared__ float wt[8];
    int e = blockIdx.x, t = threadIdx.x; // 128
    int dst = ei[NE + e];
    if (t < 8) wt[t] = alpha[e*8+t] / (den[dst*8+t] + 1e-16f);
    for (int i = t; i < 475; i += 128) {
        int r = i/19, p = i%19;
        wi[r][p] = winv[(size_t)e*475 + r*19 + c_PERM[p]];
    }
    __syncthreads();
    const float* hh = h3 + (size_t)e*2432;
    float w = wt[t >> 4];
    #pragma unroll
    for (int p = 0; p < 19; p++) m[p][t] = hh[p*128 + t] * w;
    __syncthreads();
    float* no = node + (size_t)dst*3200;
    #pragma unroll
    for (int r = 0; r < 25; r++) {
        float acc = 0.f;
        #pragma unroll
        for (int p = 0; p < 19; p++) acc += wi[r][p]*m[p][t];
        atomicAdd(&no[r*128 + t], acc);
    }
}

// ---------- output projection ----------------------------------------------
__global__ void k_proj(const float* __restrict__ node, const float* __restrict__ pw,
                       const float* __restrict__ pb, float* __restrict__ outp)
{
    __shared__ float wt[128*65];
    int bid = blockIdx.x;      // n*5 + l
    int n = bid / 5, l = bid % 5;
    int t = threadIdx.x;       // 64
    for (int i = t; i < 8192; i += 64) {
        int o = i >> 7, c = i & 127;
        wt[c*65 + o] = pw[l*8192 + i];
    }
    __syncthreads();
    int i0 = l*l, i1 = (l+1)*(l+1);
    for (int i = i0; i < i1; i++) {
        const float* nr = node + (size_t)n*3200 + i*128;
        float acc = (i == 0) ? pb[t] : 0.f;
        #pragma unroll 8
        for (int c = 0; c < 128; c++) acc += nr[c] * wt[c*65 + t];
        outp[(size_t)n*1600 + i*64 + t] = acc;
    }
}

// ----------------------------------------------------------------------------
extern "C" void kernel_launch(void* const* d_in, const int* in_sizes, int n_in,
                              void* d_out, int out_size)
{
    const float* x    = (const float*)d_in[0];
    const float* ed   = (const float*)d_in[1];
    const int*   ei   = (const int*)  d_in[2];
    const float* wig  = (const float*)d_in[3];
    const float* winv = (const float*)d_in[4];
    const float* tgr  = (const float*)d_in[5];
    const float* fgr  = (const float*)d_in[6];
    const float* rw1  = (const float*)d_in[7];
    const float* rb1  = (const float*)d_in[8];
    const float* rg1  = (const float*)d_in[9];
    const float* rbe1 = (const float*)d_in[10];
    const float* rw2  = (const float*)d_in[11];
    const float* rb2  = (const float*)d_in[12];
    const float* rg2  = (const float*)d_in[13];
    const float* rbe2 = (const float*)d_in[14];
    const float* rw3  = (const float*)d_in[15];
    const float* rb3  = (const float*)d_in[16];
    const float* c1w0 = (const float*)d_in[17];
    const float* c1b0 = (const float*)d_in[18];
    const float* c1w1 = (const float*)d_in[19];
    const float* c1w2 = (const float*)d_in[20];
    const float* c2w0 = (const float*)d_in[21];
    const float* c2b0 = (const float*)d_in[22];
    const float* c2w1 = (const float*)d_in[23];
    const float* c2w2 = (const float*)d_in[24];
    const float* alng = (const float*)d_in[25];
    const float* alnb = (const float*)d_in[26];
    const float* adot = (const float*)d_in[27];
    const float* pw   = (const float*)d_in[28];
    const float* pb   = (const float*)d_in[29];
    float* outp = (float*)d_out;

    void* p;
    cudaGetSymbolAddress(&p, g_hid);  float* hid  = (float*)p;
    cudaGetSymbolAddress(&p, g_rad);  float* rad  = (float*)p;
    cudaGetSymbolAddress(&p, g_sm);   float* sm   = (float*)p;
    cudaGetSymbolAddress(&p, g_tmp0); float* tmp0 = (float*)p;
    cudaGetSymbolAddress(&p, g_h1);   float* h1   = (float*)p;
    cudaGetSymbolAddress(&p, g_h2);   float* h2   = (float*)p;
    cudaGetSymbolAddress(&p, g_h3);   float* h3   = (float*)p;
    cudaGetSymbolAddress(&p, g_alf);  float* alf  = (float*)p;
    cudaGetSymbolAddress(&p, g_amax); unsigned int* amax = (unsigned int*)p;
    cudaGetSymbolAddress(&p, g_den);  float* den  = (float*)p;
    cudaGetSymbolAddress(&p, g_node); float* node = (float*)p;

    const int MB = (NE + 63) / 64;   // 313

    k_init<<<(NN*3200 + 255)/256, 256>>>(node, amax, den);
    k_radial<<<512, 64>>>(ed, rw1, rb1, rg1, rbe1, rw2, rb2, rg2, rbe2, hid);
    k_gemm<<<dim3(MB, 24), 256>>>(hid, 64, rw3, rb3, rad, 1536, NE, 1536, 64);
    k_wigner<<<NE, 128>>>(x, ei, wig, rad, sm);
    // conv1
    k_gemm<<<dim3(MB, 14), 256>>>(sm, 2432, c1w0, c1b0, tmp0, 896, NE, 896, 640);
    k_cgemm<<<dim3(MB, 4), 256>>>(sm+640,  sm+1152, 2432, c1w1, 256*512,
                                  h1+320, h1+576, 1216, NE, 256, 512);
    k_cgemm<<<dim3(MB, 3), 256>>>(sm+1664, sm+2048, 2432, c1w2, 192*384,
                                  h1+832, h1+1024, 1216, NE, 192, 384);
    // grid nonlinearity
    k_grid<<<NE/2, 128>>>(tmp0, h1, tgr, fgr, h2);
    // conv2
    k_gemm<<<dim3(MB, 10), 256>>>(h2, 1216, c2w0, c2b0, h3, 2432, NE, 640, 320);
    k_cgemm<<<dim3(MB, 8), 256>>>(h2+320, h2+576, 1216, c2w1, 512*256,
                                  h3+640,  h3+1152, 2432, NE, 512, 256);
    k_cgemm<<<dim3(MB, 6), 256>>>(h2+832, h2+1024, 1216, c2w2, 384*192,
                                  h3+1664, h3+2048, 2432, NE, 384, 192);
    // attention
    k_alpha1<<<NE, 256>>>(tmp0, ei, alng, alnb, adot, alf, amax);
    k_alpha2<<<(NE*8 + 255)/256, 256>>>(alf, ei, amax, den);
    k_attn<<<NE, 128>>>(h3, winv, alf, den, ei, node);
    // projection
    k_proj<<<NN*5, 64>>>(node, pw, pb, outp);
}